// round 2
// baseline (speedup 1.0000x reference)
#include <cuda_runtime.h>
#include <cuda_bf16.h>

// JPEG quality-99 luma path only (chroma provably constant for grayscale-replicated input).
// Per channel (14x14): minmax-normalize, *255, edge-pad to 16x16, 4x (8x8 DCT -> diff_round
// quant/dequant -> 8x8 IDCT), crop, clip, denormalize.

__constant__ float YQ[64] = {
    16.f, 11.f, 10.f, 16.f, 24.f, 40.f, 51.f, 61.f,
    12.f, 12.f, 14.f, 19.f, 26.f, 58.f, 60.f, 55.f,
    14.f, 13.f, 16.f, 24.f, 40.f, 57.f, 69.f, 56.f,
    14.f, 17.f, 22.f, 29.f, 51.f, 87.f, 80.f, 62.f,
    18.f, 22.f, 37.f, 56.f, 68.f,109.f,103.f, 77.f,
    24.f, 35.f, 55.f, 64.f, 81.f,104.f,113.f, 92.f,
    49.f, 64.f, 78.f, 87.f,103.f,121.f,120.f,101.f,
    72.f, 92.f, 95.f, 98.f,112.f,100.f,103.f, 99.f
};

__constant__ float ALPHA[8] = {
    0.70710678118654752f, 1.f, 1.f, 1.f, 1.f, 1.f, 1.f, 1.f
};

__global__ __launch_bounds__(256, 4)
void jpeg_y_kernel(const float* __restrict__ x, float* __restrict__ out, int nch)
{
    __shared__ float csh[8][8];        // csh[u][xx] = cos((2*xx+1)*u*pi/16)
    __shared__ float raw[4][196];
    __shared__ float bA[4][16][17];
    __shared__ float bB[4][16][17];
    __shared__ float red[4][2][2];

    const int tid = threadIdx.x;
    const int ch  = tid >> 6;          // channel slot within block (0..3)
    const int t   = tid & 63;          // thread within channel
    const int a   = t >> 3;            // 0..7  (freq row u / spatial row x)
    const int b   = t & 7;             // 0..7  (freq col v / spatial col y)

    if (tid < 64) {
        int u = tid >> 3, xx = tid & 7;
        csh[u][xx] = cospif((float)((2 * xx + 1) * u) * (1.0f / 16.0f));
    }

    const int gch = blockIdx.x * 4 + ch;
    const bool act = (gch < nch);
    const float* xp = x + (size_t)gch * 196;

    // ---- load + per-channel min/max ----
    float mn = 3.4e38f, mx = -3.4e38f;
    if (act) {
        for (int i = t; i < 196; i += 64) {
            float v = xp[i];
            raw[ch][i] = v;
            mn = fminf(mn, v);
            mx = fmaxf(mx, v);
        }
    }
    #pragma unroll
    for (int o = 16; o; o >>= 1) {
        mn = fminf(mn, __shfl_xor_sync(0xffffffffu, mn, o));
        mx = fmaxf(mx, __shfl_xor_sync(0xffffffffu, mx, o));
    }
    if ((t & 31) == 0) { red[ch][t >> 5][0] = mn; red[ch][t >> 5][1] = mx; }
    __syncthreads();

    mn = fminf(red[ch][0][0], red[ch][1][0]);
    const float rng = fmaxf(red[ch][0][1], red[ch][1][1]) - mn + 1e-5f;

    // ---- build padded 16x16, normalized to [0,255], minus 128 ----
    #pragma unroll
    for (int k = 0; k < 4; k++) {
        int idx = t + 64 * k;          // 0..255
        int y = idx >> 4, xc = idx & 15;
        int sy = min(max(y - 1, 0), 13);
        int sx = min(max(xc - 1, 0), 13);
        bB[ch][y][xc] = (raw[ch][sy * 14 + sx] - mn) / rng * 255.0f - 128.0f;
    }
    __syncthreads();

    // ---- DCT pass 1 (over columns): bA[row][v] = sum_y bB[row][y] * C[v][y] ----
    #pragma unroll
    for (int yb = 0; yb < 2; yb++)
        #pragma unroll
        for (int bc = 0; bc < 2; bc++) {
            int y = 8 * yb + a;
            float s = 0.f;
            #pragma unroll
            for (int xx = 0; xx < 8; xx++)
                s += bB[ch][y][8 * bc + xx] * csh[b][xx];
            bA[ch][y][8 * bc + b] = s;
        }
    __syncthreads();

    // ---- DCT pass 2 (over rows) + quant + diff_round + dequant ----
    const float aa = ALPHA[a] * ALPHA[b];
    const float qs = YQ[a * 8 + b] * 0.02f;   // factor for quality 99
    #pragma unroll
    for (int br = 0; br < 2; br++)
        #pragma unroll
        for (int bc = 0; bc < 2; bc++) {
            float s = 0.f;
            #pragma unroll
            for (int y = 0; y < 8; y++)
                s += bA[ch][8 * br + y][8 * bc + b] * csh[a][y];
            float D  = 0.25f * aa * s;
            float qd = D / qs;
            float r  = rintf(qd);             // round-half-even == jnp.round
            float d  = qd - r;
            float q  = r + d * d * d;         // diff_round
            // store dequantized coeff with IDCT alpha folded in
            bB[ch][8 * br + a][8 * bc + b] = (q * qs) * aa;
        }
    __syncthreads();

    // ---- IDCT pass 1 (over v): bA[u][y] = sum_v e[u][v] * C[v][y] ----
    #pragma unroll
    for (int br = 0; br < 2; br++)
        #pragma unroll
        for (int bc = 0; bc < 2; bc++) {
            float s = 0.f;
            #pragma unroll
            for (int v = 0; v < 8; v++)
                s += bB[ch][8 * br + a][8 * bc + v] * csh[v][b];
            bA[ch][8 * br + a][8 * bc + b] = s;
        }
    __syncthreads();

    // ---- IDCT pass 2 (over u) + crop + clip + denormalize + store ----
    #pragma unroll
    for (int br = 0; br < 2; br++)
        #pragma unroll
        for (int bc = 0; bc < 2; bc++) {
            float s = 0.f;
            #pragma unroll
            for (int u = 0; u < 8; u++)
                s += csh[u][a] * bA[ch][8 * br + u][8 * bc + b];
            float p = 0.25f * s + 128.0f;     // reconstructed padded pixel
            int i = 8 * br + a - 1;
            int j = 8 * bc + b - 1;
            if (act && (unsigned)i < 14u && (unsigned)j < 14u) {
                float c = fminf(fmaxf(p, 0.0f), 255.0f) * (1.0f / 255.0f);
                out[(size_t)gch * 196 + i * 14 + j] = c * rng + mn;
            }
        }
}

extern "C" void kernel_launch(void* const* d_in, const int* in_sizes, int n_in,
                              void* d_out, int out_size)
{
    const float* x = (const float*)d_in[0];
    float* out = (float*)d_out;
    int nch = in_sizes[0] / 196;               // 32*1024 = 32768 channels of 14x14
    int blocks = (nch + 3) / 4;
    jpeg_y_kernel<<<blocks, 256>>>(x, out, nch);
}

// round 6
// speedup vs baseline: 3.1237x; 3.1237x over previous
#include <cuda_runtime.h>
#include <cuda_bf16.h>

// JPEG q=99 luma-only path (chroma provably constant for grayscale-replicated input).
// One thread per 8x8 padded tile, transforms fully in registers with literal coefficients.

#define C1f 0.98078528040323044913f
#define C2f 0.92387953251128675613f
#define C3f 0.83146961230254523708f
#define C4f 0.70710678118654752440f
#define C5f 0.55557023301960222474f
#define C6f 0.38268343236508977173f
#define C7f 0.19509032201612826785f

__device__ __forceinline__ void dct8(const float in[8], float out[8]) {
    float s0 = in[0] + in[7], s1 = in[1] + in[6], s2 = in[2] + in[5], s3 = in[3] + in[4];
    float d0 = in[0] - in[7], d1 = in[1] - in[6], d2 = in[2] - in[5], d3 = in[3] - in[4];
    out[0] = (s0 + s3) + (s1 + s2);
    out[4] = C4f * ((s0 + s3) - (s1 + s2));
    out[2] = C2f*s0 + C6f*s1 - C6f*s2 - C2f*s3;
    out[6] = C6f*s0 - C2f*s1 + C2f*s2 - C6f*s3;
    out[1] = C1f*d0 + C3f*d1 + C5f*d2 + C7f*d3;
    out[3] = C3f*d0 - C7f*d1 - C1f*d2 - C5f*d3;
    out[5] = C5f*d0 - C1f*d1 + C7f*d2 + C3f*d3;
    out[7] = C7f*d0 - C5f*d1 + C3f*d2 - C1f*d3;
}

__device__ __forceinline__ void idct8(const float e[8], float out[8]) {
    float ev0 = e[0] + C2f*e[2] + C4f*e[4] + C6f*e[6];
    float ev1 = e[0] + C6f*e[2] - C4f*e[4] - C2f*e[6];
    float ev2 = e[0] - C6f*e[2] - C4f*e[4] + C2f*e[6];
    float ev3 = e[0] - C2f*e[2] + C4f*e[4] - C6f*e[6];
    float od0 = C1f*e[1] + C3f*e[3] + C5f*e[5] + C7f*e[7];
    float od1 = C3f*e[1] - C7f*e[3] - C1f*e[5] - C5f*e[7];
    float od2 = C5f*e[1] - C1f*e[3] + C7f*e[5] + C3f*e[7];
    float od3 = C7f*e[1] - C5f*e[3] + C3f*e[5] - C1f*e[7];
    out[0] = ev0 + od0;  out[7] = ev0 - od0;
    out[1] = ev1 + od1;  out[6] = ev1 - od1;
    out[2] = ev2 + od2;  out[5] = ev2 - od2;
    out[3] = ev3 + od3;  out[4] = ev3 - od3;
}

// 128 threads = 32 channels, 4 tiles (threads) per channel.
#define NCH_BLK 32
#define STRIDE 197   // 197 % 32 == 5 -> conflict-free window access

__global__ __launch_bounds__(128, 4)
void jpeg_y_kernel(const float* __restrict__ x, float* __restrict__ out, int nch)
{
    // function-local constexpr arrays: visible in device code, fold to literals
    constexpr float YQT[64] = {
        16.f, 11.f, 10.f, 16.f, 24.f, 40.f, 51.f, 61.f,
        12.f, 12.f, 14.f, 19.f, 26.f, 58.f, 60.f, 55.f,
        14.f, 13.f, 16.f, 24.f, 40.f, 57.f, 69.f, 56.f,
        14.f, 17.f, 22.f, 29.f, 51.f, 87.f, 80.f, 62.f,
        18.f, 22.f, 37.f, 56.f, 68.f,109.f,103.f, 77.f,
        24.f, 35.f, 55.f, 64.f, 81.f,104.f,113.f, 92.f,
        49.f, 64.f, 78.f, 87.f,103.f,121.f,120.f,101.f,
        72.f, 92.f, 95.f, 98.f,112.f,100.f,103.f, 99.f
    };
    constexpr float AL[8] = { C4f, 1.f, 1.f, 1.f, 1.f, 1.f, 1.f, 1.f };

    __shared__ float sh[NCH_BLK * STRIDE];

    const int tid  = threadIdx.x;
    const int chs  = tid >> 2;       // 0..31 channel slot
    const int tile = tid & 3;        // 0..3  tile within channel
    const int br   = tile >> 1, bc = tile & 1;
    const int gch0 = blockIdx.x * NCH_BLK;

    // ---- stage input (coalesced global -> shared, skewed by channel) ----
    #pragma unroll
    for (int k = 0; k < 49; k++) {
        int i  = tid + 128 * k;               // 0 .. 6271
        int ch = i / 196;
        float v = (gch0 + ch < nch) ? x[(size_t)gch0 * 196 + i] : 0.0f;
        sh[i + ch] = v;                       // == sh[ch*197 + (i - ch*196)]
    }
    __syncthreads();

    // ---- per-channel min/max (4 threads x 49 values, shuffle-combine) ----
    const int base = chs * STRIDE;
    float mn = 3.4e38f, mx = -3.4e38f;
    #pragma unroll
    for (int k = 0; k < 49; k++) {
        float v = sh[base + tile * 49 + k];
        mn = fminf(mn, v); mx = fmaxf(mx, v);
    }
    mn = fminf(mn, __shfl_xor_sync(0xffffffffu, mn, 1));
    mx = fmaxf(mx, __shfl_xor_sync(0xffffffffu, mx, 1));
    mn = fminf(mn, __shfl_xor_sync(0xffffffffu, mn, 2));
    mx = fmaxf(mx, __shfl_xor_sync(0xffffffffu, mx, 2));
    const float rng = mx - mn + 1e-5f;
    const float sc  = 255.0f / rng;

    float A[64];

    // ---- pass 1: row DCT (over y) from padded window ----
    #pragma unroll
    for (int xr = 0; xr < 8; xr++) {
        int row = min(max(8 * br + xr - 1, 0), 13);
        float w[8], r[8];
        #pragma unroll
        for (int y = 0; y < 8; y++) {
            int col = min(max(8 * bc + y - 1, 0), 13);
            w[y] = (sh[base + row * 14 + col] - mn) * sc - 128.0f;
        }
        dct8(w, r);
        #pragma unroll
        for (int v = 0; v < 8; v++) A[xr * 8 + v] = r[v];
    }

    // ---- pass 2: column DCT (over x) + diff_round quant/dequant ----
    #pragma unroll
    for (int v = 0; v < 8; v++) {
        float c[8], d[8];
        #pragma unroll
        for (int xr = 0; xr < 8; xr++) c[xr] = A[xr * 8 + v];
        dct8(c, d);
        #pragma unroll
        for (int u = 0; u < 8; u++) {
            float aa = AL[u] * AL[v];                 // compile-time literal
            float qs = YQT[u * 8 + v] * 0.02f;        // compile-time literal
            float D  = 0.25f * aa * d[u];
            float qd = D * (1.0f / qs);               // literal reciprocal
            float rr = rintf(qd);                     // round-half-even == jnp.round
            float dd = qd - rr;
            float q  = rr + dd * dd * dd;
            A[u * 8 + v] = (q * qs) * aa;             // dequant with IDCT alpha folded
        }
    }

    // ---- pass 3: IDCT over u (columns) ----
    #pragma unroll
    for (int v = 0; v < 8; v++) {
        float c[8], s[8];
        #pragma unroll
        for (int u = 0; u < 8; u++) c[u] = A[u * 8 + v];
        idct8(c, s);
        #pragma unroll
        for (int xr = 0; xr < 8; xr++) A[xr * 8 + v] = s[xr];
    }

    __syncthreads();   // all input shared reads done before output overwrites

    // ---- pass 4: IDCT over v (rows) + clip + denorm -> shared ----
    const float dsc = rng * (1.0f / 255.0f);
    #pragma unroll
    for (int xr = 0; xr < 8; xr++) {
        int i = 8 * br + xr - 1;
        if ((unsigned)i < 14u) {
            float e[8], p[8];
            #pragma unroll
            for (int v = 0; v < 8; v++) e[v] = A[xr * 8 + v];
            idct8(e, p);
            #pragma unroll
            for (int y = 0; y < 8; y++) {
                int j = 8 * bc + y - 1;
                if ((unsigned)j < 14u) {
                    float pv = 0.25f * p[y] + 128.0f;
                    pv = fminf(fmaxf(pv, 0.0f), 255.0f);
                    sh[base + i * 14 + j] = pv * dsc + mn;
                }
            }
        }
    }
    __syncthreads();

    // ---- de-stage output (shared -> coalesced global) ----
    #pragma unroll
    for (int k = 0; k < 49; k++) {
        int i  = tid + 128 * k;
        int ch = i / 196;
        if (gch0 + ch < nch)
            out[(size_t)gch0 * 196 + i] = sh[i + ch];
    }
}

extern "C" void kernel_launch(void* const* d_in, const int* in_sizes, int n_in,
                              void* d_out, int out_size)
{
    const float* x = (const float*)d_in[0];
    float* out = (float*)d_out;
    int nch = in_sizes[0] / 196;                  // 32*1024 channels of 14x14
    int blocks = (nch + NCH_BLK - 1) / NCH_BLK;   // 1024
    jpeg_y_kernel<<<blocks, 128>>>(x, out, nch);
}